// round 9
// baseline (speedup 1.0000x reference)
#include <cuda_runtime.h>
#include <math.h>

#define Bc 2
#define Sc 2048
#define Tc 8
#define Cc 128
#define Kc 16
#define Hc 4
#define Fc 130        // C+2
#define Nc 32768
#define Uc 520        // H*(C+2)
#define UP 528        // g_Wu row width / g_WoT row count (pad zeroed)
#define UTS 532       // ut row stride (532 % 32 == 20 -> conflict-free A frags)
#define NBS 140       // nb row stride

typedef unsigned int u32;

// ---- weights scratch (__device__ globals; no allocations allowed) ----
__device__ float g_Wu[Cc*UP];             // [c][j] tf32 bits, pad j>=520 zero
__device__ float g_WoT[UP*Cc];            // [j][c'] tf32 bits, pad rows zero
__device__ int   g_is64;

__device__ __forceinline__ u32 tf32_of(float f) {
    u32 u;
    asm("cvt.rna.tf32.f32 %0, %1;" : "=r"(u) : "f"(f));
    return u;
}
__device__ __forceinline__ void mma_tf32(float* d, u32 a0, u32 a1, u32 a2, u32 a3,
                                         u32 b0, u32 b1) {
    asm("mma.sync.aligned.m16n8k8.row.col.f32.tf32.tf32.f32 "
        "{%0,%1,%2,%3}, {%4,%5,%6,%7}, {%8,%9}, {%0,%1,%2,%3};"
        : "+f"(d[0]), "+f"(d[1]), "+f"(d[2]), "+f"(d[3])
        : "r"(a0), "r"(a1), "r"(a2), "r"(a3), "r"(b0), "r"(b1));
}

// ---------------------------------------------------------------------------
__global__ void k_detect(const unsigned int* __restrict__ p) {
    __shared__ int any;
    if (threadIdx.x == 0) any = 0;
    __syncthreads();
    for (int i = threadIdx.x; i < 4096; i += blockDim.x)
        if (p[2*i + 1] != 0u) any = 1;
    __syncthreads();
    if (threadIdx.x == 0) g_is64 = (any == 0) ? 1 : 0;
}

// ---------------------------------------------------------------------------
// k0: combined weights, tf32-rounded, padded with zeros.
// ---------------------------------------------------------------------------
__global__ void k0_combine(const float* __restrict__ Wq, const float* __restrict__ Wk,
                           const float* __restrict__ Wv, const float* __restrict__ Wp) {
    int i = blockIdx.x * blockDim.x + threadIdx.x;
    if (i >= Cc*UP) return;
    int c = i / UP;
    int j = i % UP;
    float su = 0.f, so = 0.f;
    if (j < Uc) {
        int h = j / Fc;
        int f = j % Fc;
        #pragma unroll
        for (int d = 0; d < 32; d++) {
            int hd = h*32 + d;
            su = fmaf(Wq[hd*Cc + c], Wk[hd*(Cc+2) + f], su);
            so = fmaf(Wp[c*Cc + hd], Wv[hd*(Cc+2) + f], so);
        }
        su *= rsqrtf(32.f);
    }
    g_Wu[c*UP + j]  = __uint_as_float(tf32_of(su));
    g_WoT[j*Cc + c] = __uint_as_float(tf32_of(so));
}

// ---------------------------------------------------------------------------
// km: fused mega-kernel. 32 rows per block, 256 threads (8 warps).
//   Phase A: U-tile = x-tile @ Wu (tf32 MMA, Wu streamed in 6x88-col chunks)
//   Phase B: per-warp attention (4 rows each); nbar overwrites ut row (tf32)
//   Phase C: out = ut @ WoT + bias (tf32 MMA, WoT streamed in 6x88-k chunks)
// smem: ut[32][532] | wst[13312] | nbb[8][16][140] (aliases xs) | small[640]
// ---------------------------------------------------------------------------
__global__ __launch_bounds__(256) void km(const float* __restrict__ x,
                                          const void* __restrict__ sidx,
                                          const float* __restrict__ swgt,
                                          const float* __restrict__ ali,
                                          const float* __restrict__ dstp,
                                          const float* __restrict__ bp,
                                          float* __restrict__ out) {
    extern __shared__ float sm[];
    float* ut     = sm;                         // 32*532 = 17024 words
    float* wst    = sm + 17024;                 // 13312 words (128*104 / 88*136+pad)
    float* nbb    = sm + 17024 + 13312;         // 17920 words (8 warps x 16 x 140)
    float* smallp = nbb + 17920;                // 8 x 80 words

    int tid = threadIdx.x;
    int w = tid >> 5, lane = tid & 31;
    int gid = lane >> 2, tig = lane & 3;
    int base = blockIdx.x * 32;
    int bt = base >> 11;
    int b = bt >> 3, t = bt & 7;
    int s0 = base & 2047;
    int strip = w & 1, m0 = strip * 16, wq = w >> 1;

    // ================= Phase A: U-tile = x @ Wu =================
    {
        u32* xs = (u32*)nbb;    // 32 x 132 (aliases nb region; dead after A)
        for (int idx = tid; idx < 1024; idx += 256) {
            int r = idx >> 5, c4 = idx & 31;
            float4 v = ((const float4*)(x + ((size_t)((b*Sc + s0 + r)*Tc + t))*Cc))[c4];
            uint4 u = make_uint4(tf32_of(v.x), tf32_of(v.y), tf32_of(v.z), tf32_of(v.w));
            *((uint4*)&xs[r*132 + c4*4]) = u;
        }
    }
    {
        u32* xs = (u32*)nbb;
        u32* wstu = (u32*)wst;
        int rA0 = (m0 + gid) * 132;
        int rA1 = (m0 + gid + 8) * 132;
        for (int ch = 0; ch < 6; ch++) {
            __syncthreads();
            // stage Wu chunk [128 k][88 n] -> stride 104
            for (int idx = tid; idx < 2816; idx += 256) {
                int c = idx / 22, q = idx - c*22;
                uint4 wv = ((const uint4*)(g_Wu + (size_t)c*UP + ch*88))[q];
                *((uint4*)&wst[c*104 + q*4]) = *((uint4*)&wv);
            }
            __syncthreads();

            float acc[3][4];
            #pragma unroll
            for (int i = 0; i < 3; i++)
                #pragma unroll
                for (int e = 0; e < 4; e++) acc[i][e] = 0.f;

            #pragma unroll
            for (int ks = 0; ks < 16; ks++) {
                int kk = ks * 8;
                u32 a0 = xs[rA0 + kk + tig];
                u32 a1 = xs[rA1 + kk + tig];
                u32 a2 = xs[rA0 + kk + tig + 4];
                u32 a3 = xs[rA1 + kk + tig + 4];
                #pragma unroll
                for (int i = 0; i < 3; i++) {
                    int j8 = wq + 4*i;
                    if (j8 < 11) {
                        u32 b0 = wstu[(kk + tig)*104 + gid + 8*j8];
                        u32 b1 = wstu[(kk + tig + 4)*104 + gid + 8*j8];
                        mma_tf32(acc[i], a0, a1, a2, a3, b0, b1);
                    }
                }
            }
            #pragma unroll
            for (int i = 0; i < 3; i++) {
                int j8 = wq + 4*i;
                if (j8 < 11) {
                    int j = ch*88 + j8*8 + 2*tig;
                    ut[(m0 + gid    )*UTS + j    ] = acc[i][0];
                    ut[(m0 + gid    )*UTS + j + 1] = acc[i][1];
                    ut[(m0 + gid + 8)*UTS + j    ] = acc[i][2];
                    ut[(m0 + gid + 8)*UTS + j + 1] = acc[i][3];
                }
            }
        }
    }
    __syncthreads();   // all U rows visible to all warps

    // ================= Phase B: per-warp attention (4 rows each) =========
    {
        float* nb   = nbb + w*2240;          // [16][140]
        float* attn = smallp + w*80;         // [k][4]
        float* logw = smallp + w*80 + 64;    // [16]
        int k = lane & 15, half = lane >> 4;
        int kg = lane >> 3, l8 = lane & 7;
        size_t xbase = ((size_t)(b*Sc))*Tc*Cc + (size_t)t*Cc;

        for (int rep = 0; rep < 4; rep++) {
            int row = w + 8*rep;
            int n = base + row;

            int myjn;
            if (g_is64) myjn = (int)((const long long*)sidx)[(size_t)n*Kc + k];
            else        myjn = ((const int*)sidx)[(size_t)n*Kc + k];

            #pragma unroll
            for (int set = 0; set < 4; set++) {
                int kk2 = set*4 + kg;
                int jn = __shfl_sync(0xffffffffu, myjn, kk2);
                const float4* srck = (const float4*)(x + xbase + (size_t)jn*Tc*Cc);
                #pragma unroll
                for (int q = 0; q < 4; q++) {
                    int f4 = l8 + 8*q;
                    *((float4*)&nb[kk2*NBS + f4*4]) = srck[f4];
                }
            }
            if (half == 0) {
                nb[k*NBS + 128] = ali [(size_t)n*Kc + k];
                nb[k*NBS + 129] = dstp[(size_t)n*Kc + k];
            } else {
                #pragma unroll
                for (int e = 0; e < 6; e++) nb[k*NBS + 130 + e] = 0.f;
            }
            if (lane < Kc)
                logw[lane] = __logf(swgt[(size_t)n*Kc + lane] + 1e-6f);
            __syncwarp();

            // logits via 17 m16n8k8 tf32 MMAs; B read straight from ut row
            float d[4] = {0.f, 0.f, 0.f, 0.f};
            {
                const float* nbr0 = nb + gid*NBS;
                const float* nbr1 = nb + (gid + 8)*NBS;
                const float* urow = ut + row*UTS + gid*130;
                bool hv = (gid < 4);
                #pragma unroll
                for (int ks = 0; ks < 17; ks++) {
                    int kk = ks * 8;
                    u32 a0 = tf32_of(nbr0[kk + tig]);
                    u32 a1 = tf32_of(nbr1[kk + tig]);
                    u32 a2 = tf32_of(nbr0[kk + tig + 4]);
                    u32 a3 = tf32_of(nbr1[kk + tig + 4]);
                    int f0 = kk + tig, f1 = f0 + 4;
                    u32 b0 = (hv && f0 < Fc) ? tf32_of(urow[f0]) : 0u;
                    u32 b1 = (hv && f1 < Fc) ? tf32_of(urow[f1]) : 0u;
                    mma_tf32(d, a0, a1, a2, a3, b0, b1);
                }
            }
            {
                float lw0 = logw[gid];
                float lw1 = logw[gid + 8];
                d[0] += lw0; d[1] += lw0;
                d[2] += lw1; d[3] += lw1;
            }
            // softmax over k (xor 4,8,16 across gid lanes)
            {
                float m0v = fmaxf(d[0], d[2]);
                #pragma unroll
                for (int o = 4; o <= 16; o <<= 1)
                    m0v = fmaxf(m0v, __shfl_xor_sync(0xffffffffu, m0v, o));
                float e0 = __expf(d[0] - m0v), e2 = __expf(d[2] - m0v);
                float sum0 = e0 + e2;
                #pragma unroll
                for (int o = 4; o <= 16; o <<= 1)
                    sum0 += __shfl_xor_sync(0xffffffffu, sum0, o);
                float a0v = e0 / sum0, a2v = e2 / sum0;

                float m1v = fmaxf(d[1], d[3]);
                #pragma unroll
                for (int o = 4; o <= 16; o <<= 1)
                    m1v = fmaxf(m1v, __shfl_xor_sync(0xffffffffu, m1v, o));
                float e1 = __expf(d[1] - m1v), e3 = __expf(d[3] - m1v);
                float sum1 = e1 + e3;
                #pragma unroll
                for (int o = 4; o <= 16; o <<= 1)
                    sum1 += __shfl_xor_sync(0xffffffffu, sum1, o);
                float a1v = e1 / sum1, a3v = e3 / sum1;

                if (tig < 2) {
                    attn[(gid    )*4 + 2*tig    ] = a0v;
                    attn[(gid    )*4 + 2*tig + 1] = a1v;
                    attn[(gid + 8)*4 + 2*tig    ] = a2v;
                    attn[(gid + 8)*4 + 2*tig + 1] = a3v;
                }
            }
            __syncwarp();

            // nbar (scalar fp32) -> overwrite ut row as tf32 bits
            {
                float4 acc4[4];
                float4 acc4t = make_float4(0.f, 0.f, 0.f, 0.f);
                #pragma unroll
                for (int q = 0; q < 4; q++) acc4[q] = make_float4(0.f, 0.f, 0.f, 0.f);
                #pragma unroll
                for (int kk2 = 0; kk2 < Kc; kk2++) {
                    float4 a = *((const float4*)&attn[kk2*4]);
                    const float* nbr = nb + kk2*NBS;
                    #pragma unroll
                    for (int q = 0; q < 4; q++) {
                        float v = nbr[lane + 32*q];
                        acc4[q].x = fmaf(a.x, v, acc4[q].x);
                        acc4[q].y = fmaf(a.y, v, acc4[q].y);
                        acc4[q].z = fmaf(a.z, v, acc4[q].z);
                        acc4[q].w = fmaf(a.w, v, acc4[q].w);
                    }
                    if (lane < 2) {
                        float v = nbr[128 + lane];
                        acc4t.x = fmaf(a.x, v, acc4t.x);
                        acc4t.y = fmaf(a.y, v, acc4t.y);
                        acc4t.z = fmaf(a.z, v, acc4t.z);
                        acc4t.w = fmaf(a.w, v, acc4t.w);
                    }
                }
                u32* dstrow = (u32*)(ut + row*UTS);
                #pragma unroll
                for (int q = 0; q < 4; q++) {
                    int f = lane + 32*q;
                    dstrow[0*Fc + f] = tf32_of(acc4[q].x);
                    dstrow[1*Fc + f] = tf32_of(acc4[q].y);
                    dstrow[2*Fc + f] = tf32_of(acc4[q].z);
                    dstrow[3*Fc + f] = tf32_of(acc4[q].w);
                }
                if (lane < 2) {
                    int f = 128 + lane;
                    dstrow[0*Fc + f] = tf32_of(acc4t.x);
                    dstrow[1*Fc + f] = tf32_of(acc4t.y);
                    dstrow[2*Fc + f] = tf32_of(acc4t.z);
                    dstrow[3*Fc + f] = tf32_of(acc4t.w);
                }
                if (lane < 12) dstrow[Uc + lane] = 0u;   // zero pad 520..531
            }
            __syncwarp();
        }
    }

    // ================= Phase C: out = ut @ WoT + bias =================
    {
        u32* utu  = (u32*)ut;
        u32* wstu = (u32*)wst;
        int rC0 = (m0 + gid) * UTS;
        int rC1 = (m0 + gid + 8) * UTS;

        float acc[4][4];
        #pragma unroll
        for (int i = 0; i < 4; i++)
            #pragma unroll
            for (int e = 0; e < 4; e++) acc[i][e] = 0.f;

        for (int ch = 0; ch < 6; ch++) {
            __syncthreads();   // nbar done (ch=0) / prior MMA done
            // stage WoT chunk [88 k][128 n] -> stride 136
            for (int idx = tid; idx < 2816; idx += 256) {
                int kk2 = idx >> 5, q = idx & 31;
                uint4 wv = ((const uint4*)(g_WoT + (size_t)(ch*88 + kk2)*Cc))[q];
                *((uint4*)&wst[kk2*136 + q*4]) = *((uint4*)&wv);
            }
            __syncthreads();

            #pragma unroll
            for (int ks = 0; ks < 11; ks++) {
                int kg2 = ch*88 + ks*8;   // global j index into ut
                int kl  = ks*8;           // local row in wst
                u32 a0 = utu[rC0 + kg2 + tig];
                u32 a1 = utu[rC1 + kg2 + tig];
                u32 a2 = utu[rC0 + kg2 + tig + 4];
                u32 a3 = utu[rC1 + kg2 + tig + 4];
                #pragma unroll
                for (int i = 0; i < 4; i++) {
                    int n8 = wq + 4*i;
                    u32 b0 = wstu[(kl + tig)*136 + gid + 8*n8];
                    u32 b1 = wstu[(kl + tig + 4)*136 + gid + 8*n8];
                    mma_tf32(acc[i], a0, a1, a2, a3, b0, b1);
                }
            }
        }

        #pragma unroll
        for (int i = 0; i < 4; i++) {
            int n8 = wq + 4*i;
            int cp = n8*8 + 2*tig;
            float2 bv = *((const float2*)&bp[cp]);
            int sA = s0 + m0 + gid;
            int sB = sA + 8;
            *((float2*)(out + ((size_t)((b*Sc + sA)*Tc + t))*Cc + cp)) =
                make_float2(acc[i][0] + bv.x, acc[i][1] + bv.y);
            *((float2*)(out + ((size_t)((b*Sc + sB)*Tc + t))*Cc + cp)) =
                make_float2(acc[i][2] + bv.x, acc[i][3] + bv.y);
        }
    }
}

// ---------------------------------------------------------------------------
extern "C" void kernel_launch(void* const* d_in, const int* in_sizes, int n_in,
                              void* d_out, int out_size) {
    const float* x    = (const float*)d_in[0];
    const void*  sidx = d_in[1];
    const float* swgt = (const float*)d_in[2];
    const float* ali  = (const float*)d_in[3];
    const float* dstp = (const float*)d_in[4];
    const float* Wq   = (const float*)d_in[5];
    const float* Wk   = (const float*)d_in[6];
    const float* Wv   = (const float*)d_in[7];
    const float* Wp   = (const float*)d_in[8];
    const float* bp   = (const float*)d_in[9];
    float* out = (float*)d_out;

    const int KM_SMEM = (17024 + 13312 + 17920 + 640) * 4;   // 195,584 B
    cudaFuncSetAttribute(km, cudaFuncAttributeMaxDynamicSharedMemorySize, KM_SMEM);

    k_detect<<<1, 256>>>((const unsigned int*)sidx);
    k0_combine<<<(Cc*UP + 255)/256, 256>>>(Wq, Wk, Wv, Wp);
    km<<<Nc/32, 256, KM_SMEM>>>(x, sidx, swgt, ali, dstp, bp, out);
}

// round 11
// speedup vs baseline: 1.5777x; 1.5777x over previous
#include <cuda_runtime.h>
#include <math.h>

#define Bc 2
#define Sc 2048
#define Tc 8
#define Cc 128
#define Kc 16
#define Hc 4
#define Fc 130        // C+2
#define Nc 32768
#define Uc 520        // H*(C+2)
#define UP 528        // padded row stride for U/NB
#define NBS 140       // nb row stride (conflict-free for frag loads)

typedef unsigned int u32;

// ---- scratch (__device__ globals; no allocations allowed) ----
__device__ float g_Wu[Cc*UP];             // [c][j] tf32 bits, pad j>=520 zero
__device__ float g_WoT[UP*Cc];            // [j][c'] tf32 bits, pad rows zero
__device__ float g_U[(size_t)Nc*UP];      // fp32
__device__ float g_NB[(size_t)Nc*UP];     // tf32 bits (written by k2)
__device__ int   g_is64;

__device__ __forceinline__ u32 tf32_of(float f) {
    u32 u;
    asm("cvt.rna.tf32.f32 %0, %1;" : "=r"(u) : "f"(f));
    return u;
}
__device__ __forceinline__ void mma_tf32(float* d, u32 a0, u32 a1, u32 a2, u32 a3,
                                         u32 b0, u32 b1) {
    asm("mma.sync.aligned.m16n8k8.row.col.f32.tf32.tf32.f32 "
        "{%0,%1,%2,%3}, {%4,%5,%6,%7}, {%8,%9}, {%0,%1,%2,%3};"
        : "+f"(d[0]), "+f"(d[1]), "+f"(d[2]), "+f"(d[3])
        : "r"(a0), "r"(a1), "r"(a2), "r"(a3), "r"(b0), "r"(b1));
}

// ---------------------------------------------------------------------------
// k0: combined weights (tf32, zero-padded) + int32/int64 index sniff (block 0).
// ---------------------------------------------------------------------------
__global__ void k0_combine(const float* __restrict__ Wq, const float* __restrict__ Wk,
                           const float* __restrict__ Wv, const float* __restrict__ Wp,
                           const unsigned int* __restrict__ sp) {
    __shared__ int any;
    if (blockIdx.x == 0) {
        if (threadIdx.x == 0) any = 0;
        __syncthreads();
        for (int i = threadIdx.x; i < 4096; i += blockDim.x)
            if (sp[2*i + 1] != 0u) any = 1;
        __syncthreads();
        if (threadIdx.x == 0) g_is64 = (any == 0) ? 1 : 0;
    }

    int i = blockIdx.x * blockDim.x + threadIdx.x;
    if (i >= Cc*UP) return;
    int c = i / UP;
    int j = i % UP;
    float su = 0.f, so = 0.f;
    if (j < Uc) {
        int h = j / Fc;
        int f = j % Fc;
        #pragma unroll
        for (int d = 0; d < 32; d++) {
            int hd = h*32 + d;
            su = fmaf(Wq[hd*Cc + c], Wk[hd*(Cc+2) + f], su);
            so = fmaf(Wp[c*Cc + hd], Wv[hd*(Cc+2) + f], so);
        }
        su *= rsqrtf(32.f);
    }
    g_Wu[c*UP + j]  = __uint_as_float(tf32_of(su));
    g_WoT[j*Cc + c] = __uint_as_float(tf32_of(so));
}

// ---------------------------------------------------------------------------
// k1: U = X_ @ W_u via tf32 MMA (R8 verbatim).
// ---------------------------------------------------------------------------
__global__ __launch_bounds__(256) void k1_u(const float* __restrict__ x) {
    extern __shared__ u32 sm1[];
    u32* xs = sm1;                 // 128*132
    u32* ws = sm1 + 128*132;       // 128*72
    int base = blockIdx.x * 128;
    int bt = base >> 11;
    int s0 = base & 2047;
    int b = bt >> 3, t = bt & 7;
    int tid = threadIdx.x;
    int wid = tid >> 5, lane = tid & 31, gid = lane >> 2, tig = lane & 3;
    int m0 = wid * 16;

    for (int idx = tid; idx < 4096; idx += 256) {
        int r = idx >> 5, c4 = idx & 31;
        float4 v = ((const float4*)(x + ((size_t)((b*Sc + s0 + r)*Tc + t))*Cc))[c4];
        uint4 u = make_uint4(tf32_of(v.x), tf32_of(v.y), tf32_of(v.z), tf32_of(v.w));
        *((uint4*)&xs[r*132 + c4*4]) = u;
    }
    __syncthreads();

    int rowA0 = (m0 + gid) * 132;
    int rowA1 = (m0 + gid + 8) * 132;

    for (int ch = 0; ch < 9; ch++) {
        int j0 = ch * 64;
        int jtn = (ch < 8) ? 8 : 2;
        int jw4 = jtn * 2;
        if (ch) __syncthreads();
        for (int idx = tid; idx < 128*jw4; idx += 256) {
            int c = idx / jw4, q = idx - c*jw4;
            uint4 w = ((const uint4*)(g_Wu + (size_t)c*UP + j0))[q];
            *((uint4*)&ws[c*72 + q*4]) = w;
        }
        __syncthreads();

        float acc[8][4];
        #pragma unroll
        for (int jt = 0; jt < 8; jt++)
            #pragma unroll
            for (int e = 0; e < 4; e++) acc[jt][e] = 0.f;

        #pragma unroll
        for (int ks = 0; ks < 16; ks++) {
            int kk = ks * 8;
            u32 a0 = xs[rowA0 + kk + tig];
            u32 a1 = xs[rowA1 + kk + tig];
            u32 a2 = xs[rowA0 + kk + tig + 4];
            u32 a3 = xs[rowA1 + kk + tig + 4];
            const u32* w0p = &ws[(kk + tig)*72 + gid];
            const u32* w1p = &ws[(kk + tig + 4)*72 + gid];
            #pragma unroll
            for (int jt = 0; jt < 8; jt++) {
                if (jt < jtn) {
                    mma_tf32(acc[jt], a0, a1, a2, a3, w0p[jt*8], w1p[jt*8]);
                }
            }
        }
        #pragma unroll
        for (int jt = 0; jt < 8; jt++) {
            if (jt < jtn) {
                int j = j0 + jt*8 + 2*tig;
                *((float2*)(g_U + (size_t)(base + m0 + gid    )*UP + j)) =
                    make_float2(acc[jt][0], acc[jt][1]);
                *((float2*)(g_U + (size_t)(base + m0 + gid + 8)*UP + j)) =
                    make_float2(acc[jt][2], acc[jt][3]);
            }
        }
    }
}

// ---------------------------------------------------------------------------
// k2: warp-autonomous attention (R8) minus the uT staging — logit-MMA B
// fragments are loaded straight from g_U (each element touched once; L1-hot).
// smem drops 46->37 KB, occupancy cap 4->6 blocks/SM.
// ---------------------------------------------------------------------------
__global__ __launch_bounds__(128, 5) void k2_attn(const float* __restrict__ x,
                                                  const void* __restrict__ sidx,
                                                  const float* __restrict__ swgt,
                                                  const float* __restrict__ ali,
                                                  const float* __restrict__ dstp) {
    __shared__ __align__(16) float nb[4][Kc][NBS];     // 35.8 KB
    __shared__ __align__(16) float attn_s[4][Kc][4];   // [k][h] fp32
    __shared__ float logw[4][Kc];

    int tid = threadIdx.x;
    int n4 = tid >> 5, lane = tid & 31;
    int n = blockIdx.x * 4 + n4;
    int bt = n >> 11;
    int b = bt >> 3, t = bt & 7;
    int k = lane & 15, half = lane >> 4;
    int gid = lane >> 2, tig = lane & 3;

    // ---- P0: neighbor index (one per k, lanes 0-15 authoritative) ----
    int myjn;
    if (g_is64) myjn = (int)((const long long*)sidx)[(size_t)n*Kc + k];
    else        myjn = ((const int*)sidx)[(size_t)n*Kc + k];

    // coalesced gather: kg = lane>>3 (4 rows per pass), l8 = lane&7
    {
        int kg = lane >> 3, l8 = lane & 7;
        size_t xbase = ((size_t)(b*Sc))*Tc*Cc + (size_t)t*Cc;
        #pragma unroll
        for (int set = 0; set < 4; set++) {
            int kk = set*4 + kg;
            int jn_kk = __shfl_sync(0xffffffffu, myjn, kk);
            const float4* srck = (const float4*)(x + xbase + (size_t)jn_kk*Tc*Cc);
            #pragma unroll
            for (int q = 0; q < 4; q++) {
                int f4 = l8 + 8*q;
                *((float4*)&nb[n4][kk][f4*4]) = srck[f4];
            }
        }
    }
    if (half == 0) {
        nb[n4][k][128] = ali [(size_t)n*Kc + k];
        nb[n4][k][129] = dstp[(size_t)n*Kc + k];
    } else {
        #pragma unroll
        for (int e = 0; e < 6; e++) nb[n4][k][130 + e] = 0.f;  // zero MMA pad
    }
    if (lane < Kc)
        logw[n4][lane] = __logf(swgt[(size_t)n*Kc + lane] + 1e-6f);
    __syncwarp();

    // ---- P1: logits via 17 m16n8k8 tf32 MMAs; B direct from g_U ----
    float d[4] = {0.f, 0.f, 0.f, 0.f};
    {
        const float* nbr0 = &nb[n4][gid    ][0];
        const float* nbr1 = &nb[n4][gid + 8][0];
        const float* Urow = g_U + (size_t)n*UP + gid*Fc;   // only gid<4 read
        bool hv = (gid < 4);
        #pragma unroll
        for (int ks = 0; ks < 17; ks++) {
            int kk = ks * 8;
            u32 a0 = tf32_of(nbr0[kk + tig]);
            u32 a1 = tf32_of(nbr1[kk + tig]);
            u32 a2 = tf32_of(nbr0[kk + tig + 4]);
            u32 a3 = tf32_of(nbr1[kk + tig + 4]);
            int f0 = kk + tig, f1 = f0 + 4;
            u32 b0 = (hv && f0 < Fc) ? tf32_of(Urow[f0]) : 0u;
            u32 b1 = (hv && f1 < Fc) ? tf32_of(Urow[f1]) : 0u;
            mma_tf32(d, a0, a1, a2, a3, b0, b1);
        }
    }
    {
        float lw0 = logw[n4][gid];
        float lw1 = logw[n4][gid + 8];
        d[0] += lw0; d[1] += lw0;
        d[2] += lw1; d[3] += lw1;
    }

    // ---- P2: softmax over k (reduce over gid lanes: xor 4,8,16) ----
    {
        float m0 = fmaxf(d[0], d[2]);
        #pragma unroll
        for (int o = 4; o <= 16; o <<= 1)
            m0 = fmaxf(m0, __shfl_xor_sync(0xffffffffu, m0, o));
        float e0 = __expf(d[0] - m0), e2 = __expf(d[2] - m0);
        float s0 = e0 + e2;
        #pragma unroll
        for (int o = 4; o <= 16; o <<= 1)
            s0 += __shfl_xor_sync(0xffffffffu, s0, o);
        float a0 = e0 / s0, a2 = e2 / s0;

        float m1 = fmaxf(d[1], d[3]);
        #pragma unroll
        for (int o = 4; o <= 16; o <<= 1)
            m1 = fmaxf(m1, __shfl_xor_sync(0xffffffffu, m1, o));
        float e1 = __expf(d[1] - m1), e3 = __expf(d[3] - m1);
        float s1 = e1 + e3;
        #pragma unroll
        for (int o = 4; o <= 16; o <<= 1)
            s1 += __shfl_xor_sync(0xffffffffu, s1, o);
        float a1 = e1 / s1, a3 = e3 / s1;

        if (tig < 2) {   // heads 0..3 live in tig 0,1
            attn_s[n4][gid    ][2*tig    ] = a0;
            attn_s[n4][gid    ][2*tig + 1] = a1;
            attn_s[n4][gid + 8][2*tig    ] = a2;
            attn_s[n4][gid + 8][2*tig + 1] = a3;
        }
    }
    __syncwarp();

    // ---- P3: nbar; lane = f0, scalar fp32, attn via broadcast LDS.128 ----
    {
        float4 acc[4];
        float4 acc4t = make_float4(0.f,0.f,0.f,0.f);
        #pragma unroll
        for (int q = 0; q < 4; q++) acc[q] = make_float4(0.f,0.f,0.f,0.f);
        #pragma unroll
        for (int kk = 0; kk < Kc; kk++) {
            float4 a = *((const float4*)&attn_s[n4][kk][0]);
            const float* nbr = &nb[n4][kk][0];
            #pragma unroll
            for (int q = 0; q < 4; q++) {
                float v = nbr[lane + 32*q];
                acc[q].x = fmaf(a.x, v, acc[q].x);
                acc[q].y = fmaf(a.y, v, acc[q].y);
                acc[q].z = fmaf(a.z, v, acc[q].z);
                acc[q].w = fmaf(a.w, v, acc[q].w);
            }
            if (lane < 2) {
                float v = nbr[128 + lane];
                acc4t.x = fmaf(a.x, v, acc4t.x);
                acc4t.y = fmaf(a.y, v, acc4t.y);
                acc4t.z = fmaf(a.z, v, acc4t.z);
                acc4t.w = fmaf(a.w, v, acc4t.w);
            }
        }
        u32* dst = (u32*)(g_NB + (size_t)n*UP);
        #pragma unroll
        for (int q = 0; q < 4; q++) {
            int f = lane + 32*q;
            dst[0*Fc + f] = tf32_of(acc[q].x);
            dst[1*Fc + f] = tf32_of(acc[q].y);
            dst[2*Fc + f] = tf32_of(acc[q].z);
            dst[3*Fc + f] = tf32_of(acc[q].w);
        }
        if (lane < 2) {
            int f = 128 + lane;
            dst[0*Fc + f] = tf32_of(acc4t.x);
            dst[1*Fc + f] = tf32_of(acc4t.y);
            dst[2*Fc + f] = tf32_of(acc4t.z);
            dst[3*Fc + f] = tf32_of(acc4t.w);
        }
        if (lane < 8) dst[Uc + lane] = 0u;   // zero pad cols
    }
}

// ---------------------------------------------------------------------------
// k3: OUT = NB @ W_oT + bp via tf32 MMA (R8 verbatim).
// ---------------------------------------------------------------------------
__global__ __launch_bounds__(256) void k3_out(const float* __restrict__ bp,
                                              float* __restrict__ out) {
    extern __shared__ u32 sm3[];
    u32* as3 = sm3;                // 128*100
    u32* ws3 = sm3 + 128*100;      // 88*136
    int base = blockIdx.x * 128;
    int bt = base >> 11;
    int s0 = base & 2047;
    int b = bt >> 3, t = bt & 7;
    int tid = threadIdx.x;
    int wid = tid >> 5, lane = tid & 31, gid = lane >> 2, tig = lane & 3;
    int m0 = wid * 16;
    int rowA0 = (m0 + gid) * 100;
    int rowA1 = (m0 + gid + 8) * 100;

    float acc[16][4];
    #pragma unroll
    for (int jt = 0; jt < 16; jt++)
        #pragma unroll
        for (int e = 0; e < 4; e++) acc[jt][e] = 0.f;

    for (int ch = 0; ch < 6; ch++) {
        if (ch) __syncthreads();
        for (int idx = tid; idx < 128*22; idx += 256) {
            int r = idx / 22, q = idx - r*22;
            uint4 v = ((const uint4*)(g_NB + (size_t)(base + r)*UP + ch*88))[q];
            *((uint4*)&as3[r*100 + q*4]) = v;
        }
        for (int idx = tid; idx < 88*32; idx += 256) {
            int kk = idx >> 5, q = idx & 31;
            uint4 w = ((const uint4*)(g_WoT + (size_t)(ch*88 + kk)*Cc))[q];
            *((uint4*)&ws3[kk*136 + q*4]) = w;
        }
        __syncthreads();

        #pragma unroll
        for (int ks = 0; ks < 11; ks++) {
            int kk = ks * 8;
            u32 a0 = as3[rowA0 + kk + tig];
            u32 a1 = as3[rowA1 + kk + tig];
            u32 a2 = as3[rowA0 + kk + tig + 4];
            u32 a3 = as3[rowA1 + kk + tig + 4];
            const u32* w0p = &ws3[(kk + tig)*136 + gid];
            const u32* w1p = &ws3[(kk + tig + 4)*136 + gid];
            #pragma unroll
            for (int jt = 0; jt < 16; jt++)
                mma_tf32(acc[jt], a0, a1, a2, a3, w0p[jt*8], w1p[jt*8]);
        }
    }

    #pragma unroll
    for (int jt = 0; jt < 16; jt++) {
        int cp = jt*8 + 2*tig;
        float2 bv = *((const float2*)&bp[cp]);
        int sA = s0 + m0 + gid;
        int sB = sA + 8;
        *((float2*)(out + ((size_t)((b*Sc + sA)*Tc + t))*Cc + cp)) =
            make_float2(acc[jt][0] + bv.x, acc[jt][1] + bv.y);
        *((float2*)(out + ((size_t)((b*Sc + sB)*Tc + t))*Cc + cp)) =
            make_float2(acc[jt][2] + bv.x, acc[jt][3] + bv.y);
    }
}

// ---------------------------------------------------------------------------
extern "C" void kernel_launch(void* const* d_in, const int* in_sizes, int n_in,
                              void* d_out, int out_size) {
    const float* x    = (const float*)d_in[0];
    const void*  sidx = d_in[1];
    const float* swgt = (const float*)d_in[2];
    const float* ali  = (const float*)d_in[3];
    const float* dstp = (const float*)d_in[4];
    const float* Wq   = (const float*)d_in[5];
    const float* Wk   = (const float*)d_in[6];
    const float* Wv   = (const float*)d_in[7];
    const float* Wp   = (const float*)d_in[8];
    const float* bp   = (const float*)d_in[9];
    float* out = (float*)d_out;

    const int SM1 = (128*132 + 128*72) * 4;
    const int SM3 = (128*100 + 88*136) * 4;
    cudaFuncSetAttribute(k1_u,   cudaFuncAttributeMaxDynamicSharedMemorySize, SM1);
    cudaFuncSetAttribute(k3_out, cudaFuncAttributeMaxDynamicSharedMemorySize, SM3);

    k0_combine<<<(Cc*UP + 255)/256, 256>>>(Wq, Wk, Wv, Wp,
                                           (const unsigned int*)sidx);
    k1_u<<<Nc/128, 256, SM1>>>(x);
    k2_attn<<<Nc/4, 128>>>(x, sidx, swgt, ali, dstp);
    k3_out<<<Nc/128, 256, SM3>>>(bp, out);
}